// round 4
// baseline (speedup 1.0000x reference)
#include <cuda_runtime.h>
#include <cuda_bf16.h>

// Scratch: exclusive prefix offsets of node_num (B up to 8192)
__device__ int g_off[8193];

// ---------------------------------------------------------------------------
// Kernel 1: single-block exclusive scan of node_num[B] -> g_off[0..B]
// 1024 threads, each handles ITEMS consecutive elements, then a
// Hillis-Steele block scan over per-thread totals in shared memory.
// ---------------------------------------------------------------------------
__global__ void scan_kernel(const int* __restrict__ node_num, int B) {
    const int tid = threadIdx.x;
    const int NT = 1024;
    const int items = (B + NT - 1) / NT;

    // per-thread sequential load + local inclusive sums
    // items is small (4 for B=4096); cap at 8 for safety
    int v[8];
    int base = tid * items;
    int tsum = 0;
    #pragma unroll
    for (int i = 0; i < 8; ++i) {
        int idx = base + i;
        int val = (i < items && idx < B) ? node_num[idx] : 0;
        v[i] = tsum;          // exclusive within thread
        tsum += val;
    }

    __shared__ int s[1024];
    s[tid] = tsum;
    __syncthreads();

    // Hillis-Steele inclusive scan over thread totals
    #pragma unroll
    for (int off = 1; off < 1024; off <<= 1) {
        int add = (tid >= off) ? s[tid - off] : 0;
        __syncthreads();
        s[tid] += add;
        __syncthreads();
    }

    int excl = s[tid] - tsum;  // exclusive prefix of this thread's chunk

    #pragma unroll
    for (int i = 0; i < 8; ++i) {
        int idx = base + i;
        if (i < items && idx < B) g_off[idx] = excl + v[i];
    }
    if (tid == NT - 1) g_off[B] = s[NT - 1];  // total
}

// ---------------------------------------------------------------------------
// Kernel 2: one CTA per segment. 256 threads; thread d owns feature column d.
// Rows of a segment are contiguous, so each row read is a coalesced 1KB load.
// 4-deep unroll over rows for memory-level parallelism. Epilogue computes
// sigmoid(mean . W[o] + b[o]) for o in 0..3 via warp-shuffle reduction.
// ---------------------------------------------------------------------------
__global__ __launch_bounds__(256, 8)
void segmean_kernel(const float* __restrict__ x,
                    const int*   __restrict__ node_num,
                    const float* __restrict__ W,     // [4,256]
                    const float* __restrict__ bias,  // [4]
                    float*       __restrict__ out)   // [B,4]
{
    const int b   = blockIdx.x;
    const int d   = threadIdx.x;            // feature column, 0..255
    const int cnt = node_num[b];
    const int start = g_off[b];

    const float* p = x + (size_t)start * 256 + d;

    float s0 = 0.f, s1 = 0.f, s2 = 0.f, s3 = 0.f;
    int r = 0;
    for (; r + 4 <= cnt; r += 4) {
        s0 += p[0];
        s1 += p[256];
        s2 += p[512];
        s3 += p[768];
        p += 1024;
    }
    for (; r < cnt; ++r) {
        s0 += *p;
        p += 256;
    }
    const float m = (s0 + s1 + s2 + s3) / (float)cnt;

    // 4 dot products: mean[256] . W[o][256]
    float p0 = m * W[d];
    float p1 = m * W[256 + d];
    float p2 = m * W[512 + d];
    float p3 = m * W[768 + d];

    #pragma unroll
    for (int off = 16; off > 0; off >>= 1) {
        p0 += __shfl_down_sync(0xFFFFFFFFu, p0, off);
        p1 += __shfl_down_sync(0xFFFFFFFFu, p1, off);
        p2 += __shfl_down_sync(0xFFFFFFFFu, p2, off);
        p3 += __shfl_down_sync(0xFFFFFFFFu, p3, off);
    }

    __shared__ float part[8][4];
    const int warp = d >> 5;
    const int lane = d & 31;
    if (lane == 0) {
        part[warp][0] = p0;
        part[warp][1] = p1;
        part[warp][2] = p2;
        part[warp][3] = p3;
    }
    __syncthreads();

    if (d < 4) {
        float acc = bias[d];
        #pragma unroll
        for (int w = 0; w < 8; ++w) acc += part[w][d];
        out[(size_t)b * 4 + d] = 1.0f / (1.0f + __expf(-acc));
    }
}

extern "C" void kernel_launch(void* const* d_in, const int* in_sizes, int n_in,
                              void* d_out, int out_size) {
    const float* x        = (const float*)d_in[0];
    const int*   node_num = (const int*)  d_in[1];
    const float* W        = (const float*)d_in[2];
    const float* bias     = (const float*)d_in[3];
    float*       out      = (float*)d_out;

    const int B = in_sizes[1];   // 4096 segments

    scan_kernel<<<1, 1024>>>(node_num, B);
    segmean_kernel<<<B, 256>>>(x, node_num, W, bias, out);
}

// round 5
// speedup vs baseline: 1.0499x; 1.0499x over previous
#include <cuda_runtime.h>
#include <cuda_bf16.h>

// Scratch: exclusive prefix offsets of node_num (B up to 8192)
__device__ int g_off[8193];

// ---------------------------------------------------------------------------
// Kernel 1: single-block exclusive scan of node_num[B] -> g_off[0..B]
// ---------------------------------------------------------------------------
__global__ void scan_kernel(const int* __restrict__ node_num, int B) {
    const int tid = threadIdx.x;
    const int NT = 1024;
    const int items = (B + NT - 1) / NT;

    int v[8];
    int base = tid * items;
    int tsum = 0;
    #pragma unroll
    for (int i = 0; i < 8; ++i) {
        int idx = base + i;
        int val = (i < items && idx < B) ? node_num[idx] : 0;
        v[i] = tsum;          // exclusive within thread
        tsum += val;
    }

    __shared__ int s[1024];
    s[tid] = tsum;
    __syncthreads();

    #pragma unroll
    for (int off = 1; off < 1024; off <<= 1) {
        int add = (tid >= off) ? s[tid - off] : 0;
        __syncthreads();
        s[tid] += add;
        __syncthreads();
    }

    int excl = s[tid] - tsum;

    #pragma unroll
    for (int i = 0; i < 8; ++i) {
        int idx = base + i;
        if (i < items && idx < B) g_off[idx] = excl + v[i];
    }
    if (tid == NT - 1) g_off[B] = s[NT - 1];
}

// ---------------------------------------------------------------------------
// Kernel 2: one CTA per segment, float4 loads.
// Thread t owns fixed columns c..c+3 with c = 4*(t&63). 256 threads x float4
// = 4 rows (4KB) per iteration; unroll 2 -> 8 rows, two LDG.128 in flight.
// Tail rows (cnt%4) handled as flat float4 elements (column ownership is
// preserved because 1024 floats == 0 mod 256).
// ---------------------------------------------------------------------------
__global__ __launch_bounds__(256, 8)
void segmean_kernel(const float* __restrict__ x,
                    const int*   __restrict__ node_num,
                    const float* __restrict__ W,     // [4,256]
                    const float* __restrict__ bias,  // [4]
                    float*       __restrict__ out)   // [B,4]
{
    const int b = blockIdx.x;
    const int t = threadIdx.x;
    const int cnt   = __ldg(&node_num[b]);
    const int start = g_off[b];

    const float4* base = reinterpret_cast<const float4*>(x + (size_t)start * 256);
    const float4* p = base + t;

    float4 sA = make_float4(0.f, 0.f, 0.f, 0.f);
    float4 sB = make_float4(0.f, 0.f, 0.f, 0.f);

    const int nIter = cnt >> 2;       // 4-row groups
    int i = 0;
    for (; i + 2 <= nIter; i += 2) {
        float4 a = p[0];
        float4 c = p[256];
        sA.x += a.x; sA.y += a.y; sA.z += a.z; sA.w += a.w;
        sB.x += c.x; sB.y += c.y; sB.z += c.z; sB.w += c.w;
        p += 512;
    }
    if (nIter & 1) {
        float4 a = p[0];
        sA.x += a.x; sA.y += a.y; sA.z += a.z; sA.w += a.w;
        p += 256;
    }
    // tail rows: (cnt & 3) * 64 float4 elements, flat
    const int tailN = (cnt & 3) << 6;
    if (t < tailN) {
        float4 a = p[0];
        sB.x += a.x; sB.y += a.y; sB.z += a.z; sB.w += a.w;
    }

    float4 s;
    s.x = sA.x + sB.x;
    s.y = sA.y + sB.y;
    s.z = sA.z + sB.z;
    s.w = sA.w + sB.w;

    // partial dot with each W row over this thread's 4 columns
    const int c4 = (t & 63) << 2;
    const float4 w0 = *reinterpret_cast<const float4*>(W + c4);
    const float4 w1 = *reinterpret_cast<const float4*>(W + 256 + c4);
    const float4 w2 = *reinterpret_cast<const float4*>(W + 512 + c4);
    const float4 w3 = *reinterpret_cast<const float4*>(W + 768 + c4);

    float p0 = s.x * w0.x + s.y * w0.y + s.z * w0.z + s.w * w0.w;
    float p1 = s.x * w1.x + s.y * w1.y + s.z * w1.z + s.w * w1.w;
    float p2 = s.x * w2.x + s.y * w2.y + s.z * w2.z + s.w * w2.w;
    float p3 = s.x * w3.x + s.y * w3.y + s.z * w3.z + s.w * w3.w;

    #pragma unroll
    for (int off = 16; off > 0; off >>= 1) {
        p0 += __shfl_down_sync(0xFFFFFFFFu, p0, off);
        p1 += __shfl_down_sync(0xFFFFFFFFu, p1, off);
        p2 += __shfl_down_sync(0xFFFFFFFFu, p2, off);
        p3 += __shfl_down_sync(0xFFFFFFFFu, p3, off);
    }

    __shared__ float part[8][4];
    const int warp = t >> 5;
    const int lane = t & 31;
    if (lane == 0) {
        part[warp][0] = p0;
        part[warp][1] = p1;
        part[warp][2] = p2;
        part[warp][3] = p3;
    }
    __syncthreads();

    if (t < 4) {
        float acc = 0.f;
        #pragma unroll
        for (int w = 0; w < 8; ++w) acc += part[w][t];
        acc = bias[t] + acc / (float)cnt;
        out[(size_t)b * 4 + t] = 1.0f / (1.0f + __expf(-acc));
    }
}

extern "C" void kernel_launch(void* const* d_in, const int* in_sizes, int n_in,
                              void* d_out, int out_size) {
    const float* x        = (const float*)d_in[0];
    const int*   node_num = (const int*)  d_in[1];
    const float* W        = (const float*)d_in[2];
    const float* bias     = (const float*)d_in[3];
    float*       out      = (float*)d_out;

    const int B = in_sizes[1];   // 4096 segments

    scan_kernel<<<1, 1024>>>(node_num, B);
    segmean_kernel<<<B, 256>>>(x, node_num, W, bias, out);
}